// round 5
// baseline (speedup 1.0000x reference)
#include <cuda_runtime.h>
#include <cstdint>
#include <math.h>

// SoftPolygon B=32, P=32, 128x128.  out[b,y,x] = sigmoid(min_seg_sq * io)
//
// v4: edge-split parallelism. Two warps per row, each handling 16 of 32 edges
//     over all 128 columns (4 px/lane as 2 packed f32x2 pairs). Doubles warp
//     count (8192) to hide latency; per-warp mainloop halves. Partial mins and
//     parity masks combined via shared memory + one __syncthreads.
//
// Numerical contract: parity bit-identical to reference (integer-threshold
// + XOR-mask construction); distance path continuous => ulp-level error only.

namespace {

constexpr int NB  = 32;
constexpr int NP  = 32;
constexpr int NH  = 128;
constexpr int NW  = 128;
constexpr int RPB = 2;          // rows per block
constexpr int EPW = NP / 2;     // 16 edges per warp (2 warps per row)

__device__ __forceinline__ unsigned long long pack2(float lo, float hi) {
    unsigned long long r;
    asm("mov.b64 %0, {%1, %2};" : "=l"(r) : "f"(lo), "f"(hi));
    return r;
}

// Squared point-to-segment distance for a packed pixel pair.
__device__ __forceinline__ void seg_dist2_pair(
    unsigned long long gxp,
    unsigned long long dxinv2, unsigned long long c02,
    unsigned long long dx2,    unsigned long long x12,
    unsigned long long negdy2, unsigned long long ys12,
    float& dlo, float& dhi)
{
    asm("{\n\t"
        ".reg .b64 t, e, py, q;\n\t"
        ".reg .f32 f0, f1;\n\t"
        "fma.rn.f32x2 t, %2, %3, %4;\n\t"   // dot = gx*dxinv + c0
        "mov.b64 {f0, f1}, t;\n\t"
        "cvt.sat.f32.f32 f0, f0;\n\t"       // t = clamp(dot, 0, 1)
        "cvt.sat.f32.f32 f1, f1;\n\t"
        "mov.b64 t, {f0, f1};\n\t"
        "fma.rn.f32x2 q, t, %5, %6;\n\t"    // px = t*dx + x1
        "sub.rn.f32x2 e, %2, q;\n\t"        // e  = gx - px
        "fma.rn.f32x2 py, t, %7, %8;\n\t"   // py = t*(-dy) + ys1
        "mul.rn.f32x2 q, py, py;\n\t"
        "fma.rn.f32x2 q, e, e, q;\n\t"      // d  = e*e + py*py
        "mov.b64 {%0, %1}, q;\n\t"
        "}"
        : "=f"(dlo), "=f"(dhi)
        : "l"(gxp), "l"(dxinv2), "l"(c02), "l"(dx2), "l"(x12),
          "l"(negdy2), "l"(ys12));
}

__global__ __launch_bounds__(128) void soft_poly_kernel(
    const float* __restrict__ verts,   // (B, P, 2)
    float* __restrict__ out)           // (B, H, W)
{
    const int b    = blockIdx.y;
    const int row0 = blockIdx.x * RPB;
    const int tid  = threadIdx.x;
    const int w    = tid >> 5;         // warp 0..3
    const int lane = tid & 31;
    const int r    = w >> 1;           // local row 0..1
    const int h    = w & 1;            // edge half 0..1
    const int row  = row0 + r;
    const float gy = (float)row;

    __shared__ float vbuf[NP * 2];                  // interleaved x,y
    __shared__ ulonglong2 sE[4][EPW][3];            // packed-dup consts per warp
    __shared__ float4 smin[4][32];                  // partial mins
    __shared__ uint4  spar[4];                      // partial parity words

    if (tid < NP * 2) vbuf[tid] = verts[(size_t)b * NP * 2 + tid];
    __syncthreads();

    // ---- precompute: this warp's 16 edges for its row ----
    // lanes 16-31 duplicate lanes 0-15 (compute), only lanes<16 write sE /
    // contribute parity masks.
    unsigned int pm0, pm1, pm2, pm3;
    {
        const int il = lane & (EPW - 1);
        const int i  = h * EPW + il;              // edge index in [0,32)
        const int jp = (i + NP - 1) & (NP - 1);   // prev vertex (roll +1)
        const int kn = (i + 1) & (NP - 1);        // next vertex (roll -1)
        const float fx = vbuf[2 * i],  fy = vbuf[2 * i + 1];
        const float tx = vbuf[2 * jp], ty = vbuf[2 * jp + 1];
        const float x2 = vbuf[2 * kn], y2 = vbuf[2 * kn + 1];

        // crossing threshold, EXACT reference op order (mul, div, add)
        const bool cond = (fy > gy) != (ty > gy);
        float xint = __fadd_rn(
            __fdiv_rn(__fmul_rn(tx - fx, gy - fy), ty - fy), fx);
        if (!cond) xint = -1.0f;
        // #columns c in [0,128) with (float)c < xint — exact
        const float xc = fminf(fmaxf(ceilf(xint), 0.0f), 128.0f);
        const int ci = (int)xc;

        const bool act = (lane < EPW);
        const int n0 = min(max(ci,      0), 32);
        const int n1 = min(max(ci - 32, 0), 32);
        const int n2 = min(max(ci - 64, 0), 32);
        const int n3 = min(max(ci - 96, 0), 32);
        const unsigned int m0 = act ? (unsigned int)((1ull << n0) - 1ull) : 0u;
        const unsigned int m1 = act ? (unsigned int)((1ull << n1) - 1ull) : 0u;
        const unsigned int m2 = act ? (unsigned int)((1ull << n2) - 1ull) : 0u;
        const unsigned int m3 = act ? (unsigned int)((1ull << n3) - 1ull) : 0u;
        pm0 = __reduce_xor_sync(0xffffffffu, m0);
        pm1 = __reduce_xor_sync(0xffffffffu, m1);
        pm2 = __reduce_xor_sync(0xffffffffu, m2);
        pm3 = __reduce_xor_sync(0xffffffffu, m3);

        // segment-distance constants for edge (v_i -> v_{i+1})
        const float dx = x2 - fx, dy = y2 - fy;
        const float sq  = dx * dx + dy * dy + 1e-5f;
        const float inv = __fdiv_rn(1.0f, sq);
        const float ys1   = gy - fy;
        const float dxinv = dx * inv;
        const float c0    = (ys1 * dy - fx * dx) * inv;  // dot = gx*dxinv + c0

        if (act) {
            float2* f2 = reinterpret_cast<float2*>(&sE[w][il][0]);
            f2[0] = make_float2(dxinv, dxinv);
            f2[1] = make_float2(c0,    c0);
            f2[2] = make_float2(dx,    dx);
            f2[3] = make_float2(fx,    fx);
            f2[4] = make_float2(-dy,  -dy);
            f2[5] = make_float2(ys1,   ys1);
        }
    }
    __syncwarp();   // sE written and read by the same warp

    // ---- mainloop: 16 edges, 2 packed pixel pairs per lane ----
    const float gx0 = (float)lane;
    const unsigned long long gxpA = pack2(gx0,         gx0 + 32.0f);
    const unsigned long long gxpB = pack2(gx0 + 64.0f, gx0 + 96.0f);
    float mn0 = 3.402823466e38f, mn1 = mn0, mn2 = mn0, mn3 = mn0;

#pragma unroll
    for (int i = 0; i < EPW; ++i) {
        const ulonglong2 q0 = sE[w][i][0];
        const ulonglong2 q1 = sE[w][i][1];
        const ulonglong2 q2 = sE[w][i][2];

        float dlo, dhi;
        seg_dist2_pair(gxpA, q0.x, q0.y, q1.x, q1.y, q2.x, q2.y, dlo, dhi);
        mn0 = fminf(mn0, dlo);
        mn1 = fminf(mn1, dhi);
        seg_dist2_pair(gxpB, q0.x, q0.y, q1.x, q1.y, q2.x, q2.y, dlo, dhi);
        mn2 = fminf(mn2, dlo);
        mn3 = fminf(mn3, dhi);
    }

    // ---- combine the two edge-halves of each row ----
    smin[w][lane] = make_float4(mn0, mn1, mn2, mn3);
    if (lane == 0) spar[w] = make_uint4(pm0, pm1, pm2, pm3);
    __syncthreads();

    if (h == 0) {
        const float4 o = smin[w + 1][lane];
        const uint4  p = spar[w + 1];
        mn0 = fminf(mn0, o.x); mn1 = fminf(mn1, o.y);
        mn2 = fminf(mn2, o.z); mn3 = fminf(mn3, o.w);
        pm0 ^= p.x; pm1 ^= p.y; pm2 ^= p.z; pm3 ^= p.w;

        float* op = out + ((size_t)b * NH + row) * NW + lane;
#define EMIT(PM, MN, K) do {                                         \
        const float io = ((PM >> lane) & 1u) ? 1.0f : -1.0f;         \
        const float x  = (MN) * io;                                  \
        op[(K) * 32] = __fdividef(1.0f, 1.0f + __expf(-x));          \
    } while (0)
        EMIT(pm0, mn0, 0);
        EMIT(pm1, mn1, 1);
        EMIT(pm2, mn2, 2);
        EMIT(pm3, mn3, 3);
#undef EMIT
    }
}

}  // namespace

extern "C" void kernel_launch(void* const* d_in, const int* in_sizes, int n_in,
                              void* d_out, int out_size) {
    const float* verts = (const float*)d_in[0];
    float* out = (float*)d_out;
    dim3 grid(NH / RPB, NB);   // 64 x 32 = 2048 blocks, 4 warps each
    soft_poly_kernel<<<grid, 128>>>(verts, out);
}

// round 6
// speedup vs baseline: 1.2000x; 1.2000x over previous
#include <cuda_runtime.h>
#include <cstdint>
#include <math.h>

// SoftPolygon B=32, P=32, 128x128.  out[b,y,x] = sigmoid(min_seg_sq * io)
//
// v6: pixel-split parallelism, scalar datapath. One warp = one row-half
//     (64 columns, 2 px/lane, all 32 edges) -> 8192 warps, no combine phase.
//     Each warp duplicates its row's per-edge precompute (warp-local, lane =
//     edge) and computes only its 2 parity words. Scalar 4..2-wide ILP chains
//     beat packed f32x2 here (R4 lesson: latency-bound, not issue-bound).
//
// Numerical contract: parity bit-identical to reference via integer-threshold
// + XOR-mask; distance path continuous => ulp-level error only.

namespace {

constexpr int NB  = 32;
constexpr int NP  = 32;
constexpr int NH  = 128;
constexpr int NW  = 128;
constexpr int RPB = 2;          // rows per block (2 warps per row, 4 warps)

__global__ __launch_bounds__(128) void soft_poly_kernel(
    const float* __restrict__ verts,   // (B, P, 2)
    float* __restrict__ out)           // (B, H, W)
{
    const int b    = blockIdx.y;
    const int row0 = blockIdx.x * RPB;
    const int tid  = threadIdx.x;
    const int w    = tid >> 5;         // warp 0..3
    const int lane = tid & 31;
    const int r    = w >> 1;           // local row 0..1
    const int hp   = w & 1;            // column half 0..1
    const int row  = row0 + r;
    const float gy = (float)row;

    __shared__ float  vbuf[NP * 2];    // interleaved x,y
    __shared__ float4 sA[4][NP];       // per-warp: {x1, dx*inv, ys1*dy*inv, dx}
    __shared__ float2 sB[4][NP];       // per-warp: {dy, ys1}

    if (tid < NP * 2) vbuf[tid] = verts[(size_t)b * NP * 2 + tid];
    __syncthreads();

    // ---- per-(row, edge) precompute; edge = lane; warp-local ----
    unsigned int pmA, pmB;   // parity words for this warp's 2 column groups
    {
        const int i  = lane;
        const int jp = (i + NP - 1) & (NP - 1);   // prev vertex (roll +1)
        const int kn = (i + 1) & (NP - 1);        // next vertex (roll -1)
        const float fx = vbuf[2 * i],  fy = vbuf[2 * i + 1];
        const float tx = vbuf[2 * jp], ty = vbuf[2 * jp + 1];
        const float x2 = vbuf[2 * kn], y2 = vbuf[2 * kn + 1];

        // crossing threshold, EXACT reference op order (mul, div, add)
        const bool cond = (fy > gy) != (ty > gy);
        float xint = __fadd_rn(
            __fdiv_rn(__fmul_rn(tx - fx, gy - fy), ty - fy), fx);
        if (!cond) xint = -1.0f;
        // #columns c in [0,128) with (float)c < xint — exact
        const float xc = fminf(fmaxf(ceilf(xint), 0.0f), 128.0f);
        const int ci = (int)xc - hp * 64;   // relative to this warp's half

        const int nA = min(max(ci,      0), 32);   // cols [64hp, 64hp+32)
        const int nB = min(max(ci - 32, 0), 32);   // cols [64hp+32, 64hp+64)
        const unsigned int mA = (unsigned int)((1ull << nA) - 1ull);
        const unsigned int mB = (unsigned int)((1ull << nB) - 1ull);
        pmA = __reduce_xor_sync(0xffffffffu, mA);
        pmB = __reduce_xor_sync(0xffffffffu, mB);

        // segment-distance constants for edge (v_i -> v_{i+1})
        const float dx = x2 - fx, dy = y2 - fy;
        const float sq  = dx * dx + dy * dy + 1e-5f;
        const float inv = __fdiv_rn(1.0f, sq);
        const float ys1 = gy - fy;
        sA[w][i] = make_float4(fx, dx * inv, ys1 * dy * inv, dx);
        sB[w][i] = make_float2(dy, ys1);
    }
    __syncwarp();   // sA/sB written and read by the same warp

    // ---- mainloop: 2 pixels per lane, 32 edges ----
    const float gx0 = (float)(hp * 64 + lane);
    const float gx1 = gx0 + 32.0f;
    float mn0 = 3.402823466e38f, mn1 = mn0;

#pragma unroll
    for (int i = 0; i < NP; ++i) {
        const float4 a  = sA[w][i];
        const float2 bb = sB[w][i];

#define PIX(GX, MN) do {                                   \
        const float xs  = (GX) - a.x;                      \
        const float dot = fmaf(xs, a.y, a.z);              \
        const float t   = __saturatef(dot);                \
        const float xp  = fmaf(-t, a.w, xs);               \
        const float yp  = fmaf(-t, bb.x, bb.y);            \
        const float d   = fmaf(xp, xp, yp * yp);           \
        (MN) = fminf((MN), d);                             \
    } while (0)

        PIX(gx0, mn0);
        PIX(gx1, mn1);
#undef PIX
    }

    // ---- epilogue: sign from parity, sigmoid, store ----
    float* op = out + ((size_t)b * NH + row) * NW + hp * 64 + lane;
    {
        const float io0 = ((pmA >> lane) & 1u) ? 1.0f : -1.0f;
        const float io1 = ((pmB >> lane) & 1u) ? 1.0f : -1.0f;
        const float v0  = mn0 * io0;
        const float v1  = mn1 * io1;
        op[0]  = __fdividef(1.0f, 1.0f + __expf(-v0));
        op[32] = __fdividef(1.0f, 1.0f + __expf(-v1));
    }
}

}  // namespace

extern "C" void kernel_launch(void* const* d_in, const int* in_sizes, int n_in,
                              void* d_out, int out_size) {
    const float* verts = (const float*)d_in[0];
    float* out = (float*)d_out;
    dim3 grid(NH / RPB, NB);   // 64 x 32 = 2048 blocks, 4 warps each
    soft_poly_kernel<<<grid, 128>>>(verts, out);
}